// round 5
// baseline (speedup 1.0000x reference)
#include <cuda_runtime.h>
#include <math.h>

#define EMB    4096
#define DIM    4096
#define TPREV  8192
#define TTOT   (TPREV + 1)     // 8193
#define NCHUNK 128
#define CHUNK  (EMB / NCHUNK)  // 32
#define TPAD   8224            // padded stride for partials (mult of 32)

// Scratch (device globals — no allocation allowed)
__device__ __align__(16) float g_q[DIM];
__device__ __align__(16) float g_k[DIM];
__device__ __align__(16) float g_v[DIM];
__device__ __align__(16) float g_part[NCHUNK * TPAD];
__device__ __align__(16) float g_a[TTOT + 3];

__device__ __forceinline__ float warp_red(float v) {
#pragma unroll
    for (int off = 16; off; off >>= 1)
        v += __shfl_xor_sync(0xffffffffu, v, off);
    return v;
}

// ---------------------------------------------------------------------------
// Kernel 1: q/k/v = W{q,k,v} @ x — TWO warps per row, each with 2 batches of
// (8 W + 8 x) independent LDG.128. 24576 warps -> 3072 blocks of 256.
// ---------------------------------------------------------------------------
__global__ void qkv_kernel(const float* __restrict__ x,
                           const float* __restrict__ Wq,
                           const float* __restrict__ Wk,
                           const float* __restrict__ Wv) {
    __shared__ float part[8];
    int warp = threadIdx.x >> 5;
    int lane = threadIdx.x & 31;
    int rowInBlk = warp >> 1;                 // 0..3
    int half     = warp & 1;
    int gr  = blockIdx.x * 4 + rowInBlk;      // 0..12287
    int which = gr >> 12;
    int row   = gr & (DIM - 1);

    const float* W = (which == 0) ? Wq : (which == 1) ? Wk : Wv;
    const float4* wr = reinterpret_cast<const float4*>(W) + (size_t)row * (EMB / 4)
                       + half * (EMB / 8);
    const float4* xv = reinterpret_cast<const float4*>(x) + half * (EMB / 8);

    float acc = 0.0f;
#pragma unroll
    for (int b = 0; b < 2; b++) {             // 2 batches of 8 float4 per lane
        float4 w[8], xx[8];
#pragma unroll
        for (int j = 0; j < 8; j++) {
            int i = lane + (b * 8 + j) * 32;
            w[j]  = wr[i];
            xx[j] = __ldg(&xv[i]);
        }
#pragma unroll
        for (int j = 0; j < 8; j++)
            acc += w[j].x * xx[j].x + w[j].y * xx[j].y
                 + w[j].z * xx[j].z + w[j].w * xx[j].w;
    }
    acc = warp_red(acc);
    if (lane == 0) part[warp] = acc;
    __syncthreads();

    if (threadIdx.x < 4) {
        int gr2 = blockIdx.x * 4 + threadIdx.x;
        int wh2 = gr2 >> 12, rw2 = gr2 & (DIM - 1);
        float* dst = (wh2 == 0) ? g_q : (wh2 == 1) ? g_k : g_v;
        dst[rw2] = part[2 * threadIdx.x] + part[2 * threadIdx.x + 1];
    }
}

// ---------------------------------------------------------------------------
// Kernel 2: partial scores. Grid (8, 128), block 256 -> 8192 warps.
// Thread owns one float4 along t, chunk of 32 d, fully unrolled (all loads
// independent). Deterministic partials. t=8192 tail handled in kernel 3.
// ---------------------------------------------------------------------------
__global__ void score_partial_kernel(const float* __restrict__ Kc) {
    __shared__ float sq[CHUNK];
    int c  = blockIdx.y;
    int d0 = c * CHUNK;
    if (threadIdx.x < CHUNK)
        sq[threadIdx.x] = g_q[d0 + threadIdx.x];
    __syncthreads();

    int t4 = blockIdx.x * blockDim.x + threadIdx.x;   // 0..2047
    const float4* col = reinterpret_cast<const float4*>(Kc) +
                        (size_t)d0 * (TPREV / 4) + t4;

    float4 acc = make_float4(0.f, 0.f, 0.f, 0.f);
#pragma unroll
    for (int d = 0; d < CHUNK; d++) {
        float4 kk = col[(size_t)d * (TPREV / 4)];
        float  s  = sq[d];
        acc.x += s * kk.x; acc.y += s * kk.y;
        acc.z += s * kk.z; acc.w += s * kk.w;
    }
    reinterpret_cast<float4*>(g_part + c * TPAD)[t4] = acc;
}

// ---------------------------------------------------------------------------
// Kernel 3: reduce partials -> sigmoid scores. 33 blocks of 256:
// blocks 0..31 reduce over 128 chunks; block 32 computes the t=8192 tail.
// ---------------------------------------------------------------------------
__global__ void sigmoid_kernel() {
    if (blockIdx.x < 32) {
        int t = blockIdx.x * 256 + threadIdx.x;
        float s = 0.0f;
#pragma unroll
        for (int c = 0; c < NCHUNK; c++)
            s += g_part[c * TPAD + t];
        s *= 0.015625f;  // 1/sqrt(4096)
        g_a[t] = 1.0f / (1.0f + expf(-s));
    } else {
        __shared__ float red[256];
        float s = 0.0f;
#pragma unroll
        for (int j = 0; j < 16; j++) {
            int d = threadIdx.x + 256 * j;
            s += g_q[d] * g_k[d];
        }
        red[threadIdx.x] = s;
        __syncthreads();
#pragma unroll
        for (int w = 128; w >= 1; w >>= 1) {
            if (threadIdx.x < w) red[threadIdx.x] += red[threadIdx.x + w];
            __syncthreads();
        }
        if (threadIdx.x == 0) {
            float v = red[0] * 0.015625f;
            g_a[TPREV] = 1.0f / (1.0f + expf(-v));
        }
    }
}

// ---------------------------------------------------------------------------
// Kernel 4: z[d] = V_cache[d,:] . a[0:T] + v[d]*a[T].
// TWO warps per row, each with 4 batches of (8 V + 8 a) independent LDG.128.
// 8192 warps -> 1024 blocks of 256.
// ---------------------------------------------------------------------------
__global__ void out_kernel(const float* __restrict__ Vc, float* __restrict__ out) {
    __shared__ float part[8];
    int warp = threadIdx.x >> 5;
    int lane = threadIdx.x & 31;
    int rowInBlk = warp >> 1;
    int half     = warp & 1;
    int row = blockIdx.x * 4 + rowInBlk;

    const float4* vr = reinterpret_cast<const float4*>(Vc) + (size_t)row * (TPREV / 4)
                       + half * (TPREV / 8);
    const float4* av = reinterpret_cast<const float4*>(g_a) + half * (TPREV / 8);

    float acc = 0.0f;
#pragma unroll
    for (int b = 0; b < 4; b++) {             // 4 batches of 8 float4 per lane
        float4 v[8], a[8];
#pragma unroll
        for (int j = 0; j < 8; j++) {
            int i = lane + (b * 8 + j) * 32;
            v[j] = vr[i];
            a[j] = __ldg(&av[i]);
        }
#pragma unroll
        for (int j = 0; j < 8; j++)
            acc += v[j].x * a[j].x + v[j].y * a[j].y
                 + v[j].z * a[j].z + v[j].w * a[j].w;
    }
    acc = warp_red(acc);
    if (lane == 0) part[warp] = acc;
    __syncthreads();

    if (threadIdx.x < 4) {
        int r2 = blockIdx.x * 4 + threadIdx.x;
        out[r2] = part[2 * threadIdx.x] + part[2 * threadIdx.x + 1]
                  + g_v[r2] * g_a[TPREV];
    }
}

// ---------------------------------------------------------------------------
extern "C" void kernel_launch(void* const* d_in, const int* in_sizes, int n_in,
                              void* d_out, int out_size) {
    const float* x  = (const float*)d_in[0];
    const float* Wq = (const float*)d_in[1];
    const float* Wk = (const float*)d_in[2];
    const float* Wv = (const float*)d_in[3];
    const float* Kc = (const float*)d_in[4];
    const float* Vc = (const float*)d_in[5];
    float* out = (float*)d_out;

    qkv_kernel<<<(3 * DIM) / 4, 256>>>(x, Wq, Wk, Wv);

    dim3 sg(TPREV / (256 * 4), NCHUNK);          // (8, 128)
    score_partial_kernel<<<sg, 256>>>(Kc);

    sigmoid_kernel<<<33, 256>>>();

    out_kernel<<<DIM / 4, 256>>>(Vc, out);
}